// round 6
// baseline (speedup 1.0000x reference)
#include <cuda_runtime.h>

// ---------------------------------------------------------------------------
// GraphSAGE 3-layer, fp32. N=50000, E=600000, 128->128->128->40.
//   deg (once) -> rdeg
//   per layer: [t|s] = h @ [w_neigh|w_self]  (fused GEMM, f32x2, swizzled smem)
//              msg[dst] += t[src]            (red.global.add.v4.f32)
//              h' = act(s + msg*rdeg + b)    (elementwise)
// Layer 3 transforms to 40 dims BEFORE aggregating.
// ---------------------------------------------------------------------------

#define MAXN 50000

static __device__ float g_TS [MAXN * 256]; // fused GEMM output [t|s]
static __device__ float g_msg[MAXN * 128]; // aggregation buffer
static __device__ float g_H  [MAXN * 128]; // hidden activations
static __device__ float g_deg[MAXN];       // degree, then 1/max(deg,1)

__device__ __forceinline__ unsigned long long pack2(float x) {
    unsigned long long r;
    asm("mov.b64 %0, {%1, %1};" : "=l"(r) : "f"(x));
    return r;
}
__device__ __forceinline__ void ffma2(unsigned long long& d,
                                      unsigned long long a,
                                      unsigned long long b) {
    asm("fma.rn.f32x2 %0, %1, %2, %0;" : "+l"(d) : "l"(a), "l"(b));
}
__device__ __forceinline__ void red4(float* p, float4 v) {
    asm volatile("red.global.add.v4.f32 [%0], {%1, %2, %3, %4};"
                 :: "l"(p), "f"(v.x), "f"(v.y), "f"(v.z), "f"(v.w)
                 : "memory");
}
union U2F2 { unsigned long long u; float2 f; };

// ---------------------------------------------------------------------------
// small helpers
// ---------------------------------------------------------------------------
__global__ void zero_f4(float4* p, int n4) {
    int i = blockIdx.x * blockDim.x + threadIdx.x;
    if (i < n4) p[i] = make_float4(0.f, 0.f, 0.f, 0.f);
}

__global__ void deg_count(const int* __restrict__ dst, int E) {
    int i = blockIdx.x * blockDim.x + threadIdx.x;
    if (i < E) atomicAdd(&g_deg[dst[i]], 1.0f);
}

__global__ void rdeg_inv(int M) {
    int i = blockIdx.x * blockDim.x + threadIdx.x;
    if (i < M) g_deg[i] = 1.0f / fmaxf(g_deg[i], 1.0f);
}

// ---------------------------------------------------------------------------
// GEMM 128->256 fused: out[M x 256] = A[M x 128] @ [Wn | Ws]
// W smem layout swizzled: idx(k,C) = k*256 + p*64 + ct*2 + h,
//   where C = ct*8 + 2p + h  (ct=0..31, p=0..3, h=0..1)
// -> per-lane LDS.64 stride = 2 words -> conflict-free phases.
// ---------------------------------------------------------------------------
__global__ void __launch_bounds__(512, 1)
gemm128(const float* __restrict__ A,
        const float* __restrict__ Wn,
        const float* __restrict__ Ws,
        float* __restrict__ out, int M) {
    constexpr int ASTR = 132;
    extern __shared__ float sm[];
    float* Wsh = sm;               // 128*256
    float* Ash = sm + 128 * 256;   // 128 x ASTR

    const int tid = threadIdx.x;
    const int row0 = blockIdx.x * 128;

    // stage W (swizzled)
    for (int i = tid; i < 128 * 32; i += 512) {
        int k = i >> 5;
        int c = (i & 31) * 4;              // 0..124 step 4
        float4 wn = *reinterpret_cast<const float4*>(Wn + k * 128 + c);
        float4 ws = *reinterpret_cast<const float4*>(Ws + k * 128 + c);
        int p = (c & 7) >> 1;              // 0 or 2
        int ctn = c >> 3;
        int cts = ctn + 16;
        float* base = Wsh + k * 256;
        *reinterpret_cast<float2*>(base + p * 64 + ctn * 2)       = make_float2(wn.x, wn.y);
        *reinterpret_cast<float2*>(base + (p + 1) * 64 + ctn * 2) = make_float2(wn.z, wn.w);
        *reinterpret_cast<float2*>(base + p * 64 + cts * 2)       = make_float2(ws.x, ws.y);
        *reinterpret_cast<float2*>(base + (p + 1) * 64 + cts * 2) = make_float2(ws.z, ws.w);
    }
    // stage A tile (row-major, padded stride)
    for (int i = tid; i < 128 * 32; i += 512) {
        int r = i >> 5;
        int kc = (i & 31) * 4;
        int gr = row0 + r;
        if (gr >= M) gr = M - 1;
        float4 a = *reinterpret_cast<const float4*>(A + (size_t)gr * 128 + kc);
        *reinterpret_cast<float4*>(Ash + r * ASTR + kc) = a;
    }
    __syncthreads();

    const int ct = tid & 31;          // lane
    const int rt = tid >> 5;          // warp -> row group
    const int ct2 = ct * 2;
    const float* arow = Ash + rt * 8 * ASTR;

    unsigned long long acc[8][4];
#pragma unroll
    for (int i = 0; i < 8; i++)
#pragma unroll
        for (int p = 0; p < 4; p++) acc[i][p] = 0ull;

#pragma unroll 2
    for (int k2 = 0; k2 < 64; ++k2) {
        const int k0 = 2 * k2;
        unsigned long long w0[4], w1[4];
        const float* wb0 = Wsh + k0 * 256 + ct2;
        const float* wb1 = wb0 + 256;
#pragma unroll
        for (int p = 0; p < 4; p++) {
            w0[p] = *reinterpret_cast<const unsigned long long*>(wb0 + p * 64);
            w1[p] = *reinterpret_cast<const unsigned long long*>(wb1 + p * 64);
        }
#pragma unroll
        for (int i = 0; i < 8; i++) {
            float2 a2 = *reinterpret_cast<const float2*>(arow + i * ASTR + k0);
            unsigned long long ax = pack2(a2.x);
            unsigned long long ay = pack2(a2.y);
#pragma unroll
            for (int p = 0; p < 4; p++) ffma2(acc[i][p], ax, w0[p]);
#pragma unroll
            for (int p = 0; p < 4; p++) ffma2(acc[i][p], ay, w1[p]);
        }
    }

#pragma unroll
    for (int i = 0; i < 8; i++) {
        int gr = row0 + rt * 8 + i;
        if (gr < M) {
            float* o = out + (size_t)gr * 256 + ct * 8;
#pragma unroll
            for (int p = 0; p < 4; p += 2) {
                U2F2 u0, u1;
                u0.u = acc[i][p];
                u1.u = acc[i][p + 1];
                *reinterpret_cast<float4*>(o + 2 * p) =
                    make_float4(u0.f.x, u0.f.y, u1.f.x, u1.f.y);
            }
        }
    }
}

// ---------------------------------------------------------------------------
// GEMM 128->80 (layer 3), known-correct variant.
// ---------------------------------------------------------------------------
template <int DOUT, int CT, int RT, int TM, int TNP>
__global__ void __launch_bounds__(CT * RT, 1)
gemm_small(const float* __restrict__ A,
           const float* __restrict__ Wn,
           const float* __restrict__ Ws,
           float* __restrict__ out, int M) {
    constexpr int NOUT = 2 * DOUT;
    constexpr int BM = RT * TM;
    constexpr int NT = CT * RT;
    constexpr int ASTR = 132;

    extern __shared__ float sm[];
    float* Wsh = sm;
    float* Ash = sm + 128 * NOUT;

    const int tid = threadIdx.x;
    const int row0 = blockIdx.x * BM;

    for (int i = tid; i < 128 * (DOUT / 4); i += NT) {
        int k = i / (DOUT / 4);
        int c = (i % (DOUT / 4)) * 4;
        float4 wn = *reinterpret_cast<const float4*>(Wn + k * DOUT + c);
        float4 ws = *reinterpret_cast<const float4*>(Ws + k * DOUT + c);
        *reinterpret_cast<float4*>(Wsh + k * NOUT + c) = wn;
        *reinterpret_cast<float4*>(Wsh + k * NOUT + DOUT + c) = ws;
    }
    for (int i = tid; i < BM * 32; i += NT) {
        int r = i / 32;
        int kc = (i % 32) * 4;
        int gr = row0 + r;
        if (gr >= M) gr = M - 1;
        float4 a = *reinterpret_cast<const float4*>(A + (size_t)gr * 128 + kc);
        *reinterpret_cast<float4*>(Ash + r * ASTR + kc) = a;
    }
    __syncthreads();

    const int ct = tid % CT;
    const int rt = tid / CT;
    const int colbase = ct * (TNP * 2);
    const float* arow = Ash + rt * TM * ASTR;

    unsigned long long acc[TM][TNP];
#pragma unroll
    for (int i = 0; i < TM; i++)
#pragma unroll
        for (int p = 0; p < TNP; p++) acc[i][p] = 0ull;

#pragma unroll 4
    for (int k = 0; k < 128; ++k) {
        unsigned long long w[TNP];
#pragma unroll
        for (int p = 0; p < TNP; p++)
            w[p] = *reinterpret_cast<const unsigned long long*>(
                Wsh + k * NOUT + colbase + 2 * p);
#pragma unroll
        for (int i = 0; i < TM; i++) {
            unsigned long long aa = pack2(arow[i * ASTR + k]);
#pragma unroll
            for (int p = 0; p < TNP; p++) ffma2(acc[i][p], aa, w[p]);
        }
    }

#pragma unroll
    for (int i = 0; i < TM; i++) {
        int gr = row0 + rt * TM + i;
        if (gr < M) {
            float* o = out + (size_t)gr * NOUT + colbase;
#pragma unroll
            for (int p = 0; p < TNP; p += 2) {
                U2F2 u0, u1;
                u0.u = acc[i][p];
                u1.u = acc[i][p + 1];
                *reinterpret_cast<float4*>(o + 2 * p) =
                    make_float4(u0.f.x, u0.f.y, u1.f.x, u1.f.y);
            }
        }
    }
}

// ---------------------------------------------------------------------------
// Aggregation: msg[dst] += t[src]. 128-wide: one warp per edge, float4/lane.
// ---------------------------------------------------------------------------
__global__ void agg128(const int* __restrict__ src, const int* __restrict__ dst,
                       int E) {
    int gt = blockIdx.x * blockDim.x + threadIdx.x;
    int e = gt >> 5;
    int lane = gt & 31;
    if (e >= E) return;
    int s = src[e];
    int d = dst[e];
    float4 v = *reinterpret_cast<const float4*>(g_TS + (size_t)s * 256 + lane * 4);
    red4(g_msg + (size_t)d * 128 + lane * 4, v);
}

// 40-wide (layer 3): 10 float4 chunks per edge, flat indexing.
__global__ void agg40(const int* __restrict__ src, const int* __restrict__ dst,
                      int E) {
    int i = blockIdx.x * blockDim.x + threadIdx.x;
    if (i >= E * 10) return;
    int e = i / 10;
    int c = i - e * 10;
    int s = src[e];
    int d = dst[e];
    float4 v = *reinterpret_cast<const float4*>(g_TS + (size_t)s * 80 + c * 4);
    red4(g_msg + (size_t)d * 40 + c * 4, v);
}

// ---------------------------------------------------------------------------
// Combine: out = act(s + msg * rdeg + b).  s lives in TS[:, DOUT:2*DOUT].
// ---------------------------------------------------------------------------
template <int DOUT, bool RELU>
__global__ void comb(const float* __restrict__ TS, const float* __restrict__ b,
                     float* __restrict__ out, int M) {
    int i = blockIdx.x * blockDim.x + threadIdx.x;
    constexpr int C4 = DOUT / 4;
    if (i >= M * C4) return;
    int row = i / C4;
    int c = (i - row * C4) * 4;
    float4 s = *reinterpret_cast<const float4*>(TS + (size_t)row * (2 * DOUT) + DOUT + c);
    float4 m = *reinterpret_cast<const float4*>(g_msg + (size_t)row * DOUT + c);
    float4 bb = *reinterpret_cast<const float4*>(b + c);
    float r = g_deg[row];
    float4 v;
    v.x = s.x + m.x * r + bb.x;
    v.y = s.y + m.y * r + bb.y;
    v.z = s.z + m.z * r + bb.z;
    v.w = s.w + m.w * r + bb.w;
    if (RELU) {
        v.x = fmaxf(v.x, 0.f); v.y = fmaxf(v.y, 0.f);
        v.z = fmaxf(v.z, 0.f); v.w = fmaxf(v.w, 0.f);
    }
    *reinterpret_cast<float4*>(out + (size_t)row * DOUT + c) = v;
}

// ---------------------------------------------------------------------------
// launch
// ---------------------------------------------------------------------------
static inline int cdiv(int a, int b) { return (a + b - 1) / b; }

extern "C" void kernel_launch(void* const* d_in, const int* in_sizes, int n_in,
                              void* d_out, int out_size) {
    const float* feat = (const float*)d_in[0];
    const int*   src  = (const int*)d_in[1];
    const int*   dst  = (const int*)d_in[2];
    const float* wS0 = (const float*)d_in[3];
    const float* wN0 = (const float*)d_in[4];
    const float* b0  = (const float*)d_in[5];
    const float* wS1 = (const float*)d_in[6];
    const float* wN1 = (const float*)d_in[7];
    const float* b1  = (const float*)d_in[8];
    const float* wS2 = (const float*)d_in[9];
    const float* wN2 = (const float*)d_in[10];
    const float* b2  = (const float*)d_in[11];
    float* out = (float*)d_out;

    const int M = in_sizes[0] / 128;
    const int E = in_sizes[1];

    void *pTS, *pMsg, *pH, *pDeg;
    cudaGetSymbolAddress(&pTS, g_TS);
    cudaGetSymbolAddress(&pMsg, g_msg);
    cudaGetSymbolAddress(&pH, g_H);
    cudaGetSymbolAddress(&pDeg, g_deg);
    float* TS = (float*)pTS;
    float* H = (float*)pH;
    float4* msg4 = (float4*)pMsg;
    float4* deg4 = (float4*)pDeg;

    constexpr int SMEM_A = (128 * 256 + 128 * 132) * 4;  // 198656 B
    constexpr int SMEM_B = (128 * 80 + 128 * 132) * 4;   // 108544 B
    static bool attr_done = false;
    if (!attr_done) {
        cudaFuncSetAttribute((const void*)gemm128,
                             cudaFuncAttributeMaxDynamicSharedMemorySize, SMEM_A);
        cudaFuncSetAttribute((const void*)gemm_small<40, 10, 32, 4, 4>,
                             cudaFuncAttributeMaxDynamicSharedMemorySize, SMEM_B);
        attr_done = true;
    }

    const int gemm_blocks = cdiv(M, 128);
    const int msg128_n4 = M * 128 / 4;
    const int msg40_n4 = M * 40 / 4;

    // degree (once)
    zero_f4<<<cdiv(M, 4 * 256), 256>>>(deg4, M / 4);
    deg_count<<<cdiv(E, 256), 256>>>(dst, E);
    rdeg_inv<<<cdiv(M, 256), 256>>>(M);

    // ---- layer 1 ----
    gemm128<<<gemm_blocks, 512, SMEM_A>>>(feat, wN0, wS0, TS, M);
    zero_f4<<<cdiv(msg128_n4, 256), 256>>>(msg4, msg128_n4);
    agg128<<<cdiv(E * 32, 256), 256>>>(src, dst, E);
    comb<128, true><<<cdiv(M * 32, 256), 256>>>(TS, b0, H, M);

    // ---- layer 2 ----
    gemm128<<<gemm_blocks, 512, SMEM_A>>>(H, wN1, wS1, TS, M);
    zero_f4<<<cdiv(msg128_n4, 256), 256>>>(msg4, msg128_n4);
    agg128<<<cdiv(E * 32, 256), 256>>>(src, dst, E);
    comb<128, true><<<cdiv(M * 32, 256), 256>>>(TS, b1, H, M);

    // ---- layer 3 (40-wide, no relu) ----
    gemm_small<40, 10, 32, 4, 4><<<gemm_blocks, 320, SMEM_B>>>(H, wN2, wS2, TS, M);
    zero_f4<<<cdiv(msg40_n4, 256), 256>>>(msg4, msg40_n4);
    agg40<<<cdiv(E * 10, 256), 256>>>(src, dst, E);
    comb<40, false><<<cdiv(M * 10, 256), 256>>>(TS, b2, out, M);
}

// round 7
// speedup vs baseline: 1.8346x; 1.8346x over previous
#include <cuda_runtime.h>

// ---------------------------------------------------------------------------
// GraphSAGE 3-layer, fp32. N=50000, E=600000, 128->128->128->40.
// CSR build per call, then per layer:
//   [t|s] = h @ [w_neigh|w_self]           (R2 fused FFMA2 GEMM, proven 92us)
//   out = act(s + mean_csr(t[src]) + b)    (fused CSR gather, 4-way MLP)
// ---------------------------------------------------------------------------

#define MAXN 50000
#define MAXE 600000

static __device__ float g_TS [MAXN * 256];
static __device__ float g_H  [MAXN * 128];
static __device__ float g_rdeg[MAXN];
static __device__ int   g_degi[MAXN];
static __device__ int   g_off [MAXN + 1];
static __device__ int   g_cur [MAXN];
static __device__ int   g_esrc[MAXE];
static __device__ int   g_bsum[256];

__device__ __forceinline__ unsigned long long pack2(float x) {
    unsigned long long r;
    asm("mov.b64 %0, {%1, %1};" : "=l"(r) : "f"(x));
    return r;
}
__device__ __forceinline__ void ffma2(unsigned long long& d,
                                      unsigned long long a,
                                      unsigned long long b) {
    asm("fma.rn.f32x2 %0, %1, %2, %0;" : "+l"(d) : "l"(a), "l"(b));
}
union U2F2 { unsigned long long u; float2 f; };

// ---------------------------------------------------------------------------
// CSR build
// ---------------------------------------------------------------------------
__global__ void zero_i(int* p, int n) {
    int i = blockIdx.x * blockDim.x + threadIdx.x;
    if (i < n) p[i] = 0;
}

__global__ void count_deg(const int* __restrict__ dst, int E) {
    int i = blockIdx.x * blockDim.x + threadIdx.x;
    if (i < E) atomicAdd(&g_degi[dst[i]], 1);
}

__global__ void scan_block(const int* __restrict__ in, int* __restrict__ out,
                           int* bsum, int n) {
    int i = blockIdx.x * 256 + threadIdx.x;
    int lane = threadIdx.x & 31, w = threadIdx.x >> 5;
    int v = (i < n) ? in[i] : 0;
    int incl = v;
#pragma unroll
    for (int d = 1; d < 32; d <<= 1) {
        int t = __shfl_up_sync(0xffffffffu, incl, d);
        if (lane >= d) incl += t;
    }
    __shared__ int ws[8];
    if (lane == 31) ws[w] = incl;
    __syncthreads();
    if (threadIdx.x < 8) {
        int x = ws[threadIdx.x];
        int in2 = x;
#pragma unroll
        for (int d = 1; d < 8; d <<= 1) {
            int t = __shfl_up_sync(0xffu, in2, d);
            if (threadIdx.x >= (unsigned)d) in2 += t;
        }
        ws[threadIdx.x] = in2 - x;
        if (threadIdx.x == 7 && bsum) bsum[blockIdx.x] = in2;
    }
    __syncthreads();
    if (i < n) out[i] = ws[w] + incl - v;
}

__global__ void add_off(int M, int E) {
    int i = blockIdx.x * blockDim.x + threadIdx.x;
    if (i < M) {
        int o = g_off[i] + g_bsum[i >> 8];
        g_off[i] = o;
        g_cur[i] = o;
    } else if (i == M) {
        g_off[M] = E;
    }
}

__global__ void scatter_edges(const int* __restrict__ src,
                              const int* __restrict__ dst, int E) {
    int e = blockIdx.x * blockDim.x + threadIdx.x;
    if (e < E) {
        int slot = atomicAdd(&g_cur[dst[e]], 1);
        g_esrc[slot] = src[e];
    }
}

__global__ void make_rdeg(int M) {
    int i = blockIdx.x * blockDim.x + threadIdx.x;
    if (i < M) g_rdeg[i] = 1.0f / fmaxf((float)g_degi[i], 1.0f);
}

// ---------------------------------------------------------------------------
// Fused GEMM (exact R2 code, proven 92us / ~25us):
// out[M x 2*DOUT] = A[M x 128] @ [Wn | Ws]
// ---------------------------------------------------------------------------
template <int DOUT, int CT, int RT, int TM, int TNP>
__global__ void __launch_bounds__(CT * RT, 1)
gemm_fused(const float* __restrict__ A,
           const float* __restrict__ Wn,
           const float* __restrict__ Ws,
           float* __restrict__ out, int M) {
    constexpr int NOUT = 2 * DOUT;
    constexpr int BM = RT * TM;
    constexpr int NT = CT * RT;
    constexpr int ASTR = 132;

    extern __shared__ float sm[];
    float* Wsh = sm;
    float* Ash = sm + 128 * NOUT;

    const int tid = threadIdx.x;
    const int row0 = blockIdx.x * BM;

    for (int i = tid; i < 128 * (DOUT / 4); i += NT) {
        int k = i / (DOUT / 4);
        int c = (i % (DOUT / 4)) * 4;
        float4 wn = *reinterpret_cast<const float4*>(Wn + k * DOUT + c);
        float4 ws = *reinterpret_cast<const float4*>(Ws + k * DOUT + c);
        *reinterpret_cast<float4*>(Wsh + k * NOUT + c) = wn;
        *reinterpret_cast<float4*>(Wsh + k * NOUT + DOUT + c) = ws;
    }
    for (int i = tid; i < BM * 32; i += NT) {
        int r = i / 32;
        int kc = (i % 32) * 4;
        int gr = row0 + r;
        if (gr >= M) gr = M - 1;
        float4 a = *reinterpret_cast<const float4*>(A + (size_t)gr * 128 + kc);
        *reinterpret_cast<float4*>(Ash + r * ASTR + kc) = a;
    }
    __syncthreads();

    const int ct = tid % CT;
    const int rt = tid / CT;
    const int colbase = ct * (TNP * 2);
    const float* arow = Ash + rt * TM * ASTR;

    unsigned long long acc[TM][TNP];
#pragma unroll
    for (int i = 0; i < TM; i++)
#pragma unroll
        for (int p = 0; p < TNP; p++) acc[i][p] = 0ull;

#pragma unroll 4
    for (int k = 0; k < 128; ++k) {
        unsigned long long w[TNP];
#pragma unroll
        for (int p = 0; p < TNP; p++)
            w[p] = *reinterpret_cast<const unsigned long long*>(
                Wsh + k * NOUT + colbase + 2 * p);
#pragma unroll
        for (int i = 0; i < TM; i++) {
            unsigned long long aa = pack2(arow[i * ASTR + k]);
#pragma unroll
            for (int p = 0; p < TNP; p++) ffma2(acc[i][p], aa, w[p]);
        }
    }

#pragma unroll
    for (int i = 0; i < TM; i++) {
        int gr = row0 + rt * TM + i;
        if (gr < M) {
            float* o = out + (size_t)gr * NOUT + colbase;
#pragma unroll
            for (int p = 0; p < TNP; p += 2) {
                U2F2 u0, u1;
                u0.u = acc[i][p];
                u1.u = acc[i][p + 1];
                *reinterpret_cast<float4*>(o + 2 * p) =
                    make_float4(u0.f.x, u0.f.y, u1.f.x, u1.f.y);
            }
        }
    }
}

// ---------------------------------------------------------------------------
// Fused CSR aggregate + combine: out = act(s + mean(t[src]) + b)
// Warp per node, float4 per lane, 4 edges (independent loads) in flight.
// ---------------------------------------------------------------------------
template <bool RELU>
__global__ void aggcomb128(const float* __restrict__ TS,
                           const float* __restrict__ b,
                           float* __restrict__ out, int M) {
    int n = blockIdx.x * 8 + (threadIdx.x >> 5);
    if (n >= M) return;
    int lane = threadIdx.x & 31;
    int beg = g_off[n], end = g_off[n + 1];

    float4 a0 = make_float4(0.f, 0.f, 0.f, 0.f);
    float4 a1 = make_float4(0.f, 0.f, 0.f, 0.f);
    float4 a2 = make_float4(0.f, 0.f, 0.f, 0.f);
    float4 a3 = make_float4(0.f, 0.f, 0.f, 0.f);

    for (int j0 = beg; j0 < end; j0 += 32) {
        int cnt = min(32, end - j0);
        int s = (lane < cnt) ? g_esrc[j0 + lane] : 0;
        int t = 0;
        for (; t + 3 < cnt; t += 4) {
            int s0 = __shfl_sync(0xffffffffu, s, t);
            int s1 = __shfl_sync(0xffffffffu, s, t + 1);
            int s2 = __shfl_sync(0xffffffffu, s, t + 2);
            int s3 = __shfl_sync(0xffffffffu, s, t + 3);
            float4 v0 = *reinterpret_cast<const float4*>(TS + (size_t)s0 * 256 + lane * 4);
            float4 v1 = *reinterpret_cast<const float4*>(TS + (size_t)s1 * 256 + lane * 4);
            float4 v2 = *reinterpret_cast<const float4*>(TS + (size_t)s2 * 256 + lane * 4);
            float4 v3 = *reinterpret_cast<const float4*>(TS + (size_t)s3 * 256 + lane * 4);
            a0.x += v0.x; a0.y += v0.y; a0.z += v0.z; a0.w += v0.w;
            a1.x += v1.x; a1.y += v1.y; a1.z += v1.z; a1.w += v1.w;
            a2.x += v2.x; a2.y += v2.y; a2.z += v2.z; a2.w += v2.w;
            a3.x += v3.x; a3.y += v3.y; a3.z += v3.z; a3.w += v3.w;
        }
        for (; t < cnt; ++t) {
            int s0 = __shfl_sync(0xffffffffu, s, t);
            float4 v0 = *reinterpret_cast<const float4*>(TS + (size_t)s0 * 256 + lane * 4);
            a0.x += v0.x; a0.y += v0.y; a0.z += v0.z; a0.w += v0.w;
        }
    }
    float r = g_rdeg[n];
    float4 sf = *reinterpret_cast<const float4*>(TS + (size_t)n * 256 + 128 + lane * 4);
    float4 bb = *reinterpret_cast<const float4*>(b + lane * 4);
    float4 v;
    v.x = sf.x + (a0.x + a1.x + a2.x + a3.x) * r + bb.x;
    v.y = sf.y + (a0.y + a1.y + a2.y + a3.y) * r + bb.y;
    v.z = sf.z + (a0.z + a1.z + a2.z + a3.z) * r + bb.z;
    v.w = sf.w + (a0.w + a1.w + a2.w + a3.w) * r + bb.w;
    if (RELU) {
        v.x = fmaxf(v.x, 0.f); v.y = fmaxf(v.y, 0.f);
        v.z = fmaxf(v.z, 0.f); v.w = fmaxf(v.w, 0.f);
    }
    *reinterpret_cast<float4*>(out + (size_t)n * 128 + lane * 4) = v;
}

// 40-wide final layer (lanes 0..9 carry a float4 each; no relu)
__global__ void aggcomb40(const float* __restrict__ TS,
                          const float* __restrict__ b,
                          float* __restrict__ out, int M) {
    int n = blockIdx.x * 8 + (threadIdx.x >> 5);
    if (n >= M) return;
    int lane = threadIdx.x & 31;
    int beg = g_off[n], end = g_off[n + 1];
    bool act = lane < 10;
    int laneo = act ? lane : 0;

    float4 a0 = make_float4(0.f, 0.f, 0.f, 0.f);
    float4 a1 = make_float4(0.f, 0.f, 0.f, 0.f);
    float4 a2 = make_float4(0.f, 0.f, 0.f, 0.f);
    float4 a3 = make_float4(0.f, 0.f, 0.f, 0.f);

    for (int j0 = beg; j0 < end; j0 += 32) {
        int cnt = min(32, end - j0);
        int s = (lane < cnt) ? g_esrc[j0 + lane] : 0;
        int t = 0;
        for (; t + 3 < cnt; t += 4) {
            int s0 = __shfl_sync(0xffffffffu, s, t);
            int s1 = __shfl_sync(0xffffffffu, s, t + 1);
            int s2 = __shfl_sync(0xffffffffu, s, t + 2);
            int s3 = __shfl_sync(0xffffffffu, s, t + 3);
            float4 v0 = *reinterpret_cast<const float4*>(TS + (size_t)s0 * 80 + laneo * 4);
            float4 v1 = *reinterpret_cast<const float4*>(TS + (size_t)s1 * 80 + laneo * 4);
            float4 v2 = *reinterpret_cast<const float4*>(TS + (size_t)s2 * 80 + laneo * 4);
            float4 v3 = *reinterpret_cast<const float4*>(TS + (size_t)s3 * 80 + laneo * 4);
            a0.x += v0.x; a0.y += v0.y; a0.z += v0.z; a0.w += v0.w;
            a1.x += v1.x; a1.y += v1.y; a1.z += v1.z; a1.w += v1.w;
            a2.x += v2.x; a2.y += v2.y; a2.z += v2.z; a2.w += v2.w;
            a3.x += v3.x; a3.y += v3.y; a3.z += v3.z; a3.w += v3.w;
        }
        for (; t < cnt; ++t) {
            int s0 = __shfl_sync(0xffffffffu, s, t);
            float4 v0 = *reinterpret_cast<const float4*>(TS + (size_t)s0 * 80 + laneo * 4);
            a0.x += v0.x; a0.y += v0.y; a0.z += v0.z; a0.w += v0.w;
        }
    }
    if (act) {
        float r = g_rdeg[n];
        float4 sf = *reinterpret_cast<const float4*>(TS + (size_t)n * 80 + 40 + lane * 4);
        float4 bb = *reinterpret_cast<const float4*>(b + lane * 4);
        float4 v;
        v.x = sf.x + (a0.x + a1.x + a2.x + a3.x) * r + bb.x;
        v.y = sf.y + (a0.y + a1.y + a2.y + a3.y) * r + bb.y;
        v.z = sf.z + (a0.z + a1.z + a2.z + a3.z) * r + bb.z;
        v.w = sf.w + (a0.w + a1.w + a2.w + a3.w) * r + bb.w;
        *reinterpret_cast<float4*>(out + (size_t)n * 40 + lane * 4) = v;
    }
}

// ---------------------------------------------------------------------------
// launch
// ---------------------------------------------------------------------------
static inline int cdiv(int a, int b) { return (a + b - 1) / b; }

extern "C" void kernel_launch(void* const* d_in, const int* in_sizes, int n_in,
                              void* d_out, int out_size) {
    const float* feat = (const float*)d_in[0];
    const int*   src  = (const int*)d_in[1];
    const int*   dst  = (const int*)d_in[2];
    const float* wS0 = (const float*)d_in[3];
    const float* wN0 = (const float*)d_in[4];
    const float* b0  = (const float*)d_in[5];
    const float* wS1 = (const float*)d_in[6];
    const float* wN1 = (const float*)d_in[7];
    const float* b1  = (const float*)d_in[8];
    const float* wS2 = (const float*)d_in[9];
    const float* wN2 = (const float*)d_in[10];
    const float* b2  = (const float*)d_in[11];
    float* out = (float*)d_out;

    const int M = in_sizes[0] / 128;
    const int E = in_sizes[1];

    void *pTS, *pH, *pDegi, *pOff, *pBsum;
    cudaGetSymbolAddress(&pTS, g_TS);
    cudaGetSymbolAddress(&pH, g_H);
    cudaGetSymbolAddress(&pDegi, g_degi);
    cudaGetSymbolAddress(&pOff, g_off);
    cudaGetSymbolAddress(&pBsum, g_bsum);
    float* TS = (float*)pTS;
    float* H = (float*)pH;
    int* degi = (int*)pDegi;
    int* off = (int*)pOff;
    int* bsum = (int*)pBsum;

    constexpr int SMEM_A = (128 * 256 + 128 * 132) * 4;  // 198656 B
    constexpr int SMEM_B = (128 * 80 + 128 * 132) * 4;   // 108544 B
    static bool attr_done = false;
    if (!attr_done) {
        cudaFuncSetAttribute((const void*)gemm_fused<128, 32, 16, 8, 4>,
                             cudaFuncAttributeMaxDynamicSharedMemorySize, SMEM_A);
        cudaFuncSetAttribute((const void*)gemm_fused<40, 10, 32, 4, 4>,
                             cudaFuncAttributeMaxDynamicSharedMemorySize, SMEM_B);
        attr_done = true;
    }

    const int gemm_blocks = cdiv(M, 128);
    const int nscan = cdiv(M, 256);
    const int node_blocks = cdiv(M, 8);

    // ---- CSR build ----
    zero_i<<<cdiv(M, 256), 256>>>(degi, M);
    count_deg<<<cdiv(E, 256), 256>>>(dst, E);
    scan_block<<<nscan, 256>>>(degi, off, bsum, M);
    scan_block<<<1, 256>>>(bsum, bsum, nullptr, nscan);
    add_off<<<cdiv(M + 1, 256), 256>>>(M, E);
    scatter_edges<<<cdiv(E, 256), 256>>>(src, dst, E);
    make_rdeg<<<cdiv(M, 256), 256>>>(M);

    // ---- layer 1 ----
    gemm_fused<128, 32, 16, 8, 4><<<gemm_blocks, 512, SMEM_A>>>(feat, wN0, wS0, TS, M);
    aggcomb128<true><<<node_blocks, 256>>>(TS, b0, H, M);

    // ---- layer 2 ----
    gemm_fused<128, 32, 16, 8, 4><<<gemm_blocks, 512, SMEM_A>>>(H, wN1, wS1, TS, M);
    aggcomb128<true><<<node_blocks, 256>>>(TS, b1, H, M);

    // ---- layer 3 ----
    gemm_fused<40, 10, 32, 4, 4><<<gemm_blocks, 320, SMEM_B>>>(H, wN2, wS2, TS, M);
    aggcomb40<<<node_blocks, 256>>>(TS, b2, out, M);
}